// round 7
// baseline (speedup 1.0000x reference)
#include <cuda_runtime.h>
#include <cuda_bf16.h>

#define BB    2
#define NSEQ  2048
#define DIMX  1024
#define HH    16
#define DD    64
#define QKVS  3072
#define GM    4096
#define GN    3072
#define GK    1024

// bf16 hi/lo split scratch (precomputed inputs + QKV projection output)
__device__ __nv_bfloat16 g_xh[(size_t)GM * GK], g_xl[(size_t)GM * GK];
__device__ __nv_bfloat16 g_wh[(size_t)GN * GK], g_wl[(size_t)GN * GK];
__device__ __nv_bfloat16 g_sh[(size_t)GM * GN], g_sl[(size_t)GM * GN];

// ---------------------------------------------------------------------------
// portable PTX helpers (sm_80 feature set only)
// ---------------------------------------------------------------------------
__device__ __forceinline__ unsigned smem_u32(const void* p) {
    unsigned a;
    asm("{ .reg .u64 t; cvta.to.shared.u64 t, %1; cvt.u32.u64 %0, t; }" : "=r"(a) : "l"(p));
    return a;
}
__device__ __forceinline__ void ldsm4(unsigned* r, unsigned a) {
    asm volatile("ldmatrix.sync.aligned.m8n8.x4.shared.b16 {%0,%1,%2,%3}, [%4];"
                 : "=r"(r[0]), "=r"(r[1]), "=r"(r[2]), "=r"(r[3]) : "r"(a));
}
__device__ __forceinline__ void ldsm4t(unsigned* r, unsigned a) {
    asm volatile("ldmatrix.sync.aligned.m8n8.x4.trans.shared.b16 {%0,%1,%2,%3}, [%4];"
                 : "=r"(r[0]), "=r"(r[1]), "=r"(r[2]), "=r"(r[3]) : "r"(a));
}
__device__ __forceinline__ void mmab(float* c, const unsigned* a, unsigned b0, unsigned b1) {
    asm volatile("mma.sync.aligned.m16n8k16.row.col.f32.bf16.bf16.f32 "
                 "{%0,%1,%2,%3}, {%4,%5,%6,%7}, {%8,%9}, {%0,%1,%2,%3};"
                 : "+f"(c[0]), "+f"(c[1]), "+f"(c[2]), "+f"(c[3])
                 : "r"(a[0]), "r"(a[1]), "r"(a[2]), "r"(a[3]), "r"(b0), "r"(b1));
}
__device__ __forceinline__ void split2(float a, float b, __nv_bfloat162& h, __nv_bfloat162& l) {
    h = __float22bfloat162_rn(make_float2(a, b));
    l = __float22bfloat162_rn(make_float2(a - __bfloat162float(h.x), b - __bfloat162float(h.y)));
}
__device__ __forceinline__ unsigned u32of(__nv_bfloat162 v) {
    return *(unsigned*)&v;
}
#define CPA(dst, src) \
    asm volatile("cp.async.cg.shared.global [%0], [%1], 16;" :: "r"(dst), "l"(src))
#define CPA_COMMIT() asm volatile("cp.async.commit_group;" ::: "memory")
template <int N>
__device__ __forceinline__ void cpa_wait() {
    asm volatile("cp.async.wait_group %0;" :: "n"(N) : "memory");
}

// ---------------------------------------------------------------------------
// Kernel 0: fp32 -> bf16 hi/lo split (layout-preserving)
// ---------------------------------------------------------------------------
__global__ __launch_bounds__(256) void split_kernel(const float* __restrict__ src,
                                                    __nv_bfloat16* __restrict__ hi,
                                                    __nv_bfloat16* __restrict__ lo, int n4) {
    int i = blockIdx.x * 256 + threadIdx.x;
    if (i >= n4) return;
    float4 v = ((const float4*)src)[i];
    __nv_bfloat162 h0, l0, h1, l1;
    split2(v.x, v.y, h0, l0);
    split2(v.z, v.w, h1, l1);
    ((__nv_bfloat162*)hi)[i * 2 + 0] = h0;
    ((__nv_bfloat162*)hi)[i * 2 + 1] = h1;
    ((__nv_bfloat162*)lo)[i * 2 + 0] = l0;
    ((__nv_bfloat162*)lo)[i * 2 + 1] = l1;
}

// ---------------------------------------------------------------------------
// Kernel 1: QKV GEMM, bf16 3-term split, cp.async 3-stage ring.
// CTA 128x128, K-chunk 32. 8 warps = 4(m) x 2(n), warp tile 32x64.
// Stage (40960 B): Ah 0, Al 10240, Bh 20480, Bl 30720; pitch 80 B.
// Per chunk: wait<1>; sync; issue(c+2); compute(c). One sync per chunk.
// ---------------------------------------------------------------------------
#define GSTG 40960
__global__ __launch_bounds__(256) void qkv_gemm() {
    extern __shared__ __align__(16) unsigned char gs[];
    const unsigned sb = smem_u32(gs);
    const int tid = threadIdx.x, lane = tid & 31, wid = tid >> 5;
    const int wm = wid & 3, wn = wid >> 2;
    const int bm = blockIdx.y * 128, bn = blockIdx.x * 128;

    float acc[2][8][4];
#pragma unroll
    for (int i = 0; i < 2; i++)
#pragma unroll
        for (int j = 0; j < 8; j++)
#pragma unroll
            for (int q = 0; q < 4; q++) acc[i][j][q] = 0.f;

    const int lrow = tid >> 1, lh = (tid & 1) * 16;
    const __nv_bfloat16* xh = g_xh + (size_t)(bm + lrow) * GK + lh;
    const __nv_bfloat16* xl = g_xl + (size_t)(bm + lrow) * GK + lh;
    const __nv_bfloat16* wh = g_wh + (size_t)(bn + lrow) * GK + lh;
    const __nv_bfloat16* wl = g_wl + (size_t)(bn + lrow) * GK + lh;
    const unsigned drow = lrow * 80 + lh * 2;

    auto issue = [&](int c, int s) {
        const unsigned st = sb + s * GSTG + drow;
        const int ko = c * 32;
        CPA(st,             xh + ko);  CPA(st + 16,         xh + ko + 8);
        CPA(st + 10240,     xl + ko);  CPA(st + 10240 + 16, xl + ko + 8);
        CPA(st + 20480,     wh + ko);  CPA(st + 20480 + 16, wh + ko + 8);
        CPA(st + 30720,     wl + ko);  CPA(st + 30720 + 16, wl + ko + 8);
        CPA_COMMIT();
    };

    const unsigned aOff = (unsigned)((wm * 32 + (lane & 15)) * 80 + (lane >> 4) * 16);
    const unsigned bOff = 20480 + (unsigned)((wn * 64 + (lane & 7) + ((lane >> 4) << 3)) * 80 +
                                             ((lane >> 3) & 1) * 16);

    issue(0, 0);
    issue(1, 1);
    int stg = 0;
    for (int c = 0; c < 32; c++) {
        cpa_wait<1>();
        __syncthreads();
        if (c + 2 < 32) {
            int s2 = stg + 2; if (s2 >= 3) s2 -= 3;
            issue(c + 2, s2);
        }
        const unsigned st = sb + stg * GSTG;
        if (++stg == 3) stg = 0;
        const unsigned aAddr = st + aOff, bAddr = st + bOff;
#pragma unroll
        for (int s = 0; s < 2; s++) {
            unsigned ah[2][4], al[2][4];
            ldsm4(ah[0], aAddr + s * 32);
            ldsm4(ah[1], aAddr + 1280 + s * 32);
            ldsm4(al[0], aAddr + 10240 + s * 32);
            ldsm4(al[1], aAddr + 10240 + 1280 + s * 32);
#pragma unroll
            for (int np = 0; np < 4; np++) {
                unsigned bh[4], bl[4];
                ldsm4(bh, bAddr + np * 1280 + s * 32);
                ldsm4(bl, bAddr + 10240 + np * 1280 + s * 32);
#pragma unroll
                for (int mt = 0; mt < 2; mt++) {
                    mmab(acc[mt][2 * np + 0], ah[mt], bh[0], bh[1]);
                    mmab(acc[mt][2 * np + 0], ah[mt], bl[0], bl[1]);
                    mmab(acc[mt][2 * np + 0], al[mt], bh[0], bh[1]);
                    mmab(acc[mt][2 * np + 1], ah[mt], bh[2], bh[3]);
                    mmab(acc[mt][2 * np + 1], ah[mt], bl[2], bl[3]);
                    mmab(acc[mt][2 * np + 1], al[mt], bh[2], bh[3]);
                }
            }
        }
    }

#pragma unroll
    for (int mt = 0; mt < 2; mt++) {
        int m = bm + wm * 32 + mt * 16 + (lane >> 2);
#pragma unroll
        for (int nt = 0; nt < 8; nt++) {
            int gc = bn + wn * 64 + nt * 8 + ((lane & 3) << 1);
            float sc = (gc < DIMX) ? 0.125f : 1.0f;
            __nv_bfloat162 h, l;
            split2(acc[mt][nt][0] * sc, acc[mt][nt][1] * sc, h, l);
            *(__nv_bfloat162*)(g_sh + (size_t)m * GN + gc) = h;
            *(__nv_bfloat162*)(g_sl + (size_t)m * GN + gc) = l;
            split2(acc[mt][nt][2] * sc, acc[mt][nt][3] * sc, h, l);
            *(__nv_bfloat162*)(g_sh + (size_t)(m + 8) * GN + gc) = h;
            *(__nv_bfloat162*)(g_sl + (size_t)(m + 8) * GN + gc) = l;
        }
    }
}

// ---------------------------------------------------------------------------
// Kernel 2: attention. CTA = (b, h, 64 Q rows); 8 warps = 4 row-groups(16) x
// 2 j-halves(32). 3-term bf16 mma; exp without max-subtraction; P stays in
// REGISTERS (S C-frag == PV A-frag after bf16x2 packing); O in regs.
// cp.async 2-stage K/V; 2 CTAs/SM.
// smem bytes (row pitch 144): Qh 0, Ql 9216,
//   stage s at 18432+s*36864: Kh +0, Kl +9216, Vh +18432, Vl +27648.
// Total 92160.
// ---------------------------------------------------------------------------
#define ASTG 36864
__global__ __launch_bounds__(256, 2) void attn(float* __restrict__ out) {
    extern __shared__ __align__(16) unsigned char sm_raw[];
    const unsigned sb = smem_u32(sm_raw);
    const int tid = threadIdx.x, lane = tid & 31, wid = tid >> 5;
    const int g = wid & 3, js = wid >> 2;
    const int b = blockIdx.z, h = blockIdx.y, q0 = blockIdx.x * 64;

    // ---- K/V cp.async issue helper ----
    const int krow = tid >> 2, kq = (tid & 3) * 16;
    const size_t kvb = (size_t)(b * NSEQ + krow) * QKVS + h * 64 + kq;
    const unsigned kvd = (unsigned)((krow * 72 + kq) * 2);
    auto issue_kv = [&](int t, int s) {
        const unsigned st = sb + 18432 + s * ASTG + kvd;
        const size_t r = kvb + (size_t)t * 64 * QKVS;
        CPA(st,          g_sh + r + DIMX);     CPA(st + 16,         g_sh + r + DIMX + 8);
        CPA(st + 9216,   g_sl + r + DIMX);     CPA(st + 9216 + 16,  g_sl + r + DIMX + 8);
        CPA(st + 18432,  g_sh + r + 2 * DIMX); CPA(st + 18432 + 16, g_sh + r + 2 * DIMX + 8);
        CPA(st + 27648,  g_sl + r + 2 * DIMX); CPA(st + 27648 + 16, g_sl + r + 2 * DIMX + 8);
        CPA_COMMIT();
    };
    issue_kv(0, 0);
    issue_kv(1, 1);

    // ---- Q tile (64 rows, hi/lo) via plain LDG/STS (once) ----
    {
        size_t go = (size_t)(b * NSEQ + q0 + krow) * QKVS + h * 64 + kq;
        *(uint4*)(sm_raw + kvd)             = *(const uint4*)(g_sh + go);
        *(uint4*)(sm_raw + kvd + 16)        = *(const uint4*)(g_sh + go + 8);
        *(uint4*)(sm_raw + 9216 + kvd)      = *(const uint4*)(g_sl + go);
        *(uint4*)(sm_raw + 9216 + kvd + 16) = *(const uint4*)(g_sl + go + 8);
    }
    __syncthreads();

    // ---- persistent Q-hi frags ----
    const unsigned qA = sb + (unsigned)((g * 16 + (lane & 15)) * 144 + (lane >> 4) * 16);
    unsigned qfh[4][4];
#pragma unroll
    for (int s = 0; s < 4; s++) ldsm4(qfh[s], qA + s * 32);

    float o[8][4];
#pragma unroll
    for (int i = 0; i < 8; i++)
#pragma unroll
        for (int q = 0; q < 4; q++) o[i][q] = 0.f;
    float l0 = 0.f, l1 = 0.f;

    const unsigned kOff = (unsigned)((js * 32 + (lane & 7) + ((lane >> 4) << 3)) * 144 +
                                     ((lane >> 3) & 1) * 16);
    const unsigned vOff = 18432 + (unsigned)(((lane & 15)) * 144 + (lane >> 4) * 16);
    const int r0 = g * 16 + (lane >> 2);

    for (int t = 0; t < 32; t++) {
        cpa_wait<1>();
        __syncthreads();
        const unsigned st = sb + 18432 + (t & 1) * ASTG;
        const unsigned khA = st + kOff, klA = khA + 9216;
        const unsigned vhA = st + vOff, vlA = vhA + 9216;

        // ---- S = Q K^T (3-term) ----
        float sacc[4][4];
#pragma unroll
        for (int jt = 0; jt < 4; jt++)
#pragma unroll
            for (int q = 0; q < 4; q++) sacc[jt][q] = 0.f;
#pragma unroll
        for (int s = 0; s < 4; s++) {
            unsigned kh0[4], kh1[4], kl0[4], kl1[4], ql[4];
            ldsm4(kh0, khA + s * 32);
            ldsm4(kh1, khA + 2304 + s * 32);
            ldsm4(kl0, klA + s * 32);
            ldsm4(kl1, klA + 2304 + s * 32);
            ldsm4(ql, qA + 9216 + s * 32);
            mmab(sacc[0], qfh[s], kh0[0], kh0[1]);
            mmab(sacc[0], qfh[s], kl0[0], kl0[1]);
            mmab(sacc[0], ql,     kh0[0], kh0[1]);
            mmab(sacc[1], qfh[s], kh0[2], kh0[3]);
            mmab(sacc[1], qfh[s], kl0[2], kl0[3]);
            mmab(sacc[1], ql,     kh0[2], kh0[3]);
            mmab(sacc[2], qfh[s], kh1[0], kh1[1]);
            mmab(sacc[2], qfh[s], kl1[0], kl1[1]);
            mmab(sacc[2], ql,     kh1[0], kh1[1]);
            mmab(sacc[3], qfh[s], kh1[2], kh1[3]);
            mmab(sacc[3], qfh[s], kl1[2], kl1[3]);
            mmab(sacc[3], ql,     kh1[2], kh1[3]);
        }

        // ---- softmax (no max shift), P packed into A-frags in registers ----
        // A-frag (m16n8k16) for k-step sp: a0=pack(p[2sp][0],p[2sp][1]),
        // a1=pack(p[2sp][2],p[2sp][3]), a2/a3 same of tile 2sp+1.
        unsigned aPh[2][4], aPl[2][4];
#pragma unroll
        for (int jt = 0; jt < 4; jt++) {
            float p0 = __expf(sacc[jt][0]), p1 = __expf(sacc[jt][1]);
            float p2 = __expf(sacc[jt][2]), p3 = __expf(sacc[jt][3]);
            l0 += p0 + p1;
            l1 += p2 + p3;
            __nv_bfloat162 hh, ll;
            split2(p0, p1, hh, ll);
            aPh[jt >> 1][(jt & 1) * 2 + 0] = u32of(hh);
            aPl[jt >> 1][(jt & 1) * 2 + 0] = u32of(ll);
            split2(p2, p3, hh, ll);
            aPh[jt >> 1][(jt & 1) * 2 + 1] = u32of(hh);
            aPl[jt >> 1][(jt & 1) * 2 + 1] = u32of(ll);
        }

        // ---- O += P V (V via ldmatrix.trans; k offset = js half) ----
#pragma unroll
        for (int sp = 0; sp < 2; sp++) {
            const unsigned vk = (js * 32 + sp * 16) * 144;
#pragma unroll
            for (int db = 0; db < 4; db++) {
                unsigned vh[4], vl[4];
                ldsm4t(vh, vhA + vk + db * 32);
                ldsm4t(vl, vlA + vk + db * 32);
                mmab(o[2 * db + 0], aPh[sp], vh[0], vh[1]);
                mmab(o[2 * db + 0], aPh[sp], vl[0], vl[1]);
                mmab(o[2 * db + 0], aPl[sp], vh[0], vh[1]);
                mmab(o[2 * db + 1], aPh[sp], vh[2], vh[3]);
                mmab(o[2 * db + 1], aPh[sp], vl[2], vl[3]);
                mmab(o[2 * db + 1], aPl[sp], vh[2], vh[3]);
            }
        }
        __syncthreads();
        if (t + 2 < 32) issue_kv(t + 2, t & 1);
    }

    // ---- reduce l across quad ----
    l0 += __shfl_xor_sync(0xffffffffu, l0, 1);
    l0 += __shfl_xor_sync(0xffffffffu, l0, 2);
    l1 += __shfl_xor_sync(0xffffffffu, l1, 1);
    l1 += __shfl_xor_sync(0xffffffffu, l1, 2);

    // ---- cross-half (js) reduction via smem float scratch (reuses Q) ----
    float* red = (float*)sm_raw;                      // [64][68]
    float* redl = (float*)(sm_raw + 64 * 68 * 4);     // [64]
    if (js == 1) {
#pragma unroll
        for (int dt = 0; dt < 8; dt++) {
            *(float2*)&red[r0 * 68 + dt * 8 + (lane & 3) * 2] = make_float2(o[dt][0], o[dt][1]);
            *(float2*)&red[(r0 + 8) * 68 + dt * 8 + (lane & 3) * 2] = make_float2(o[dt][2], o[dt][3]);
        }
        if ((lane & 3) == 0) { redl[r0] = l0; redl[r0 + 8] = l1; }
    }
    __syncthreads();
    if (js == 0) {
        float inv0 = 1.f / (l0 + redl[r0]);
        float inv1 = 1.f / (l1 + redl[r0 + 8]);
        float* op0 = out + ((size_t)(b * NSEQ + q0 + r0) * HH + h) * DD;
        float* op1 = out + ((size_t)(b * NSEQ + q0 + r0 + 8) * HH + h) * DD;
#pragma unroll
        for (int dt = 0; dt < 8; dt++) {
            float2 e0 = *(const float2*)&red[r0 * 68 + dt * 8 + (lane & 3) * 2];
            float2 e1 = *(const float2*)&red[(r0 + 8) * 68 + dt * 8 + (lane & 3) * 2];
            *(float2*)&op0[dt * 8 + (lane & 3) * 2] =
                make_float2((o[dt][0] + e0.x) * inv0, (o[dt][1] + e0.y) * inv0);
            *(float2*)&op1[dt * 8 + (lane & 3) * 2] =
                make_float2((o[dt][2] + e1.x) * inv1, (o[dt][3] + e1.y) * inv1);
        }
    }
}

// ---------------------------------------------------------------------------
extern "C" void kernel_launch(void* const* d_in, const int* in_sizes, int n_in,
                              void* d_out, int out_size) {
    (void)in_sizes; (void)n_in; (void)out_size;
    const float* x = (const float*)d_in[0];
    const float* w = (const float*)d_in[1];
    float* out = (float*)d_out;

    __nv_bfloat16 *xh, *xl, *wh, *wl;
    cudaGetSymbolAddress((void**)&xh, g_xh);
    cudaGetSymbolAddress((void**)&xl, g_xl);
    cudaGetSymbolAddress((void**)&wh, g_wh);
    cudaGetSymbolAddress((void**)&wl, g_wl);

    const int gemm_smem = 3 * GSTG;                 // 122880
    const int attn_smem = 18432 + 2 * ASTG;         // 92160
    cudaFuncSetAttribute((const void*)qkv_gemm,
                         cudaFuncAttributeMaxDynamicSharedMemorySize, gemm_smem);
    cudaFuncSetAttribute((const void*)attn,
                         cudaFuncAttributeMaxDynamicSharedMemorySize, attn_smem);

    split_kernel<<<(GM * GK / 4 + 255) / 256, 256>>>(x, xh, xl, GM * GK / 4);
    split_kernel<<<(GN * GK / 4 + 255) / 256, 256>>>(w, wh, wl, GN * GK / 4);

    dim3 g1(GN / 128, GM / 128);           // (24, 32)
    qkv_gemm<<<g1, 256, gemm_smem>>>();

    dim3 g2(NSEQ / 64, HH, BB);            // (32, 16, 2)
    attn<<<g2, 256, attn_smem>>>(out);
}

// round 8
// speedup vs baseline: 1.7449x; 1.7449x over previous
#include <cuda_runtime.h>
#include <cuda_fp16.h>

#define BB    2
#define NSEQ  2048
#define DIMX  1024
#define HH    16
#define DD    64
#define QKVS  3072
#define GM    4096
#define GN    3072
#define GK    1024

// fp16 hi/lo split scratch (precomputed inputs + QKV projection output)
__device__ __half g_xh[(size_t)GM * GK], g_xl[(size_t)GM * GK];
__device__ __half g_wh[(size_t)GN * GK];
__device__ __half g_sh[(size_t)GM * GN], g_sl[(size_t)GM * GN];

// ---------------------------------------------------------------------------
// portable PTX helpers (sm_80 feature set only)
// ---------------------------------------------------------------------------
__device__ __forceinline__ unsigned smem_u32(const void* p) {
    unsigned a;
    asm("{ .reg .u64 t; cvta.to.shared.u64 t, %1; cvt.u32.u64 %0, t; }" : "=r"(a) : "l"(p));
    return a;
}
__device__ __forceinline__ void ldsm4(unsigned* r, unsigned a) {
    asm volatile("ldmatrix.sync.aligned.m8n8.x4.shared.b16 {%0,%1,%2,%3}, [%4];"
                 : "=r"(r[0]), "=r"(r[1]), "=r"(r[2]), "=r"(r[3]) : "r"(a));
}
__device__ __forceinline__ void ldsm4t(unsigned* r, unsigned a) {
    asm volatile("ldmatrix.sync.aligned.m8n8.x4.trans.shared.b16 {%0,%1,%2,%3}, [%4];"
                 : "=r"(r[0]), "=r"(r[1]), "=r"(r[2]), "=r"(r[3]) : "r"(a));
}
__device__ __forceinline__ void mmah(float* c, const unsigned* a, unsigned b0, unsigned b1) {
    asm volatile("mma.sync.aligned.m16n8k16.row.col.f32.f16.f16.f32 "
                 "{%0,%1,%2,%3}, {%4,%5,%6,%7}, {%8,%9}, {%0,%1,%2,%3};"
                 : "+f"(c[0]), "+f"(c[1]), "+f"(c[2]), "+f"(c[3])
                 : "r"(a[0]), "r"(a[1]), "r"(a[2]), "r"(a[3]), "r"(b0), "r"(b1));
}
__device__ __forceinline__ void split2h(float a, float b, __half2& h, __half2& l) {
    h = __floats2half2_rn(a, b);
    l = __floats2half2_rn(a - __low2float(h), b - __high2float(h));
}
__device__ __forceinline__ unsigned u32h(__half2 v) { return *(unsigned*)&v; }
#define CPA(dst, src) \
    asm volatile("cp.async.cg.shared.global [%0], [%1], 16;" :: "r"(dst), "l"(src))
#define CPA_COMMIT() asm volatile("cp.async.commit_group;" ::: "memory")
template <int N>
__device__ __forceinline__ void cpa_wait() {
    asm volatile("cp.async.wait_group %0;" :: "n"(N) : "memory");
}

// ---------------------------------------------------------------------------
// Kernel 0a: fp32 -> fp16 hi/lo split
// ---------------------------------------------------------------------------
__global__ __launch_bounds__(256) void split_hl(const float* __restrict__ src,
                                                __half* __restrict__ hi,
                                                __half* __restrict__ lo, int n4) {
    int i = blockIdx.x * 256 + threadIdx.x;
    if (i >= n4) return;
    float4 v = ((const float4*)src)[i];
    __half2 h0, l0, h1, l1;
    split2h(v.x, v.y, h0, l0);
    split2h(v.z, v.w, h1, l1);
    ((__half2*)hi)[i * 2 + 0] = h0;
    ((__half2*)hi)[i * 2 + 1] = h1;
    ((__half2*)lo)[i * 2 + 0] = l0;
    ((__half2*)lo)[i * 2 + 1] = l1;
}
// Kernel 0b: fp32 -> fp16 (1-term, for w)
__global__ __launch_bounds__(256) void split_h(const float* __restrict__ src,
                                               __half* __restrict__ hi, int n4) {
    int i = blockIdx.x * 256 + threadIdx.x;
    if (i >= n4) return;
    float4 v = ((const float4*)src)[i];
    ((__half2*)hi)[i * 2 + 0] = __floats2half2_rn(v.x, v.y);
    ((__half2*)hi)[i * 2 + 1] = __floats2half2_rn(v.z, v.w);
}

// ---------------------------------------------------------------------------
// Kernel 1: QKV GEMM, fp16 2-term (xh*wh + xl*wh), cp.async 3-stage ring.
// CTA 128x128, K-chunk 32. 8 warps = 4(m) x 2(n), warp tile 32x64.
// Stage (30720 B): Ah 0, Al 10240, Bh 20480; pitch 80 B. 2 CTAs/SM.
// ---------------------------------------------------------------------------
#define GSTG 30720
__global__ __launch_bounds__(256) void qkv_gemm() {
    extern __shared__ __align__(16) unsigned char gs[];
    const unsigned sb = smem_u32(gs);
    const int tid = threadIdx.x, lane = tid & 31, wid = tid >> 5;
    const int wm = wid & 3, wn = wid >> 2;
    const int bm = blockIdx.y * 128, bn = blockIdx.x * 128;

    float acc[2][8][4];
#pragma unroll
    for (int i = 0; i < 2; i++)
#pragma unroll
        for (int j = 0; j < 8; j++)
#pragma unroll
            for (int q = 0; q < 4; q++) acc[i][j][q] = 0.f;

    const int lrow = tid >> 1, lh = (tid & 1) * 16;
    const __half* xh = g_xh + (size_t)(bm + lrow) * GK + lh;
    const __half* xl = g_xl + (size_t)(bm + lrow) * GK + lh;
    const __half* wh = g_wh + (size_t)(bn + lrow) * GK + lh;
    const unsigned drow = lrow * 80 + lh * 2;

    auto issue = [&](int c, int s) {
        const unsigned st = sb + s * GSTG + drow;
        const int ko = c * 32;
        CPA(st,             xh + ko);  CPA(st + 16,         xh + ko + 8);
        CPA(st + 10240,     xl + ko);  CPA(st + 10240 + 16, xl + ko + 8);
        CPA(st + 20480,     wh + ko);  CPA(st + 20480 + 16, wh + ko + 8);
        CPA_COMMIT();
    };

    const unsigned aOff = (unsigned)((wm * 32 + (lane & 15)) * 80 + (lane >> 4) * 16);
    const unsigned bOff = 20480 + (unsigned)((wn * 64 + (lane & 7) + ((lane >> 4) << 3)) * 80 +
                                             ((lane >> 3) & 1) * 16);

    issue(0, 0);
    issue(1, 1);
    int stg = 0;
    for (int c = 0; c < 32; c++) {
        cpa_wait<1>();
        __syncthreads();
        if (c + 2 < 32) {
            int s2 = stg + 2; if (s2 >= 3) s2 -= 3;
            issue(c + 2, s2);
        }
        const unsigned st = sb + stg * GSTG;
        if (++stg == 3) stg = 0;
        const unsigned aAddr = st + aOff, bAddr = st + bOff;
#pragma unroll
        for (int s = 0; s < 2; s++) {
            unsigned ah[2][4], al[2][4];
            ldsm4(ah[0], aAddr + s * 32);
            ldsm4(ah[1], aAddr + 1280 + s * 32);
            ldsm4(al[0], aAddr + 10240 + s * 32);
            ldsm4(al[1], aAddr + 10240 + 1280 + s * 32);
#pragma unroll
            for (int np = 0; np < 4; np++) {
                unsigned bh[4];
                ldsm4(bh, bAddr + np * 1280 + s * 32);
#pragma unroll
                for (int mt = 0; mt < 2; mt++) {
                    mmah(acc[mt][2 * np + 0], ah[mt], bh[0], bh[1]);
                    mmah(acc[mt][2 * np + 0], al[mt], bh[0], bh[1]);
                    mmah(acc[mt][2 * np + 1], ah[mt], bh[2], bh[3]);
                    mmah(acc[mt][2 * np + 1], al[mt], bh[2], bh[3]);
                }
            }
        }
    }

#pragma unroll
    for (int mt = 0; mt < 2; mt++) {
        int m = bm + wm * 32 + mt * 16 + (lane >> 2);
#pragma unroll
        for (int nt = 0; nt < 8; nt++) {
            int gc = bn + wn * 64 + nt * 8 + ((lane & 3) << 1);
            float sc = (gc < DIMX) ? 0.125f : 1.0f;
            __half2 h, l;
            split2h(acc[mt][nt][0] * sc, acc[mt][nt][1] * sc, h, l);
            *(__half2*)(g_sh + (size_t)m * GN + gc) = h;
            *(__half2*)(g_sl + (size_t)m * GN + gc) = l;
            split2h(acc[mt][nt][2] * sc, acc[mt][nt][3] * sc, h, l);
            *(__half2*)(g_sh + (size_t)(m + 8) * GN + gc) = h;
            *(__half2*)(g_sl + (size_t)(m + 8) * GN + gc) = l;
        }
    }
}

// ---------------------------------------------------------------------------
// Kernel 2: attention. CTA = (b, h, 64 Q rows); 8 warps = 4 row-groups(16) x
// 2 j-halves(32). S = (qh+ql)*kh (2 mma terms, q exact), PV = P*vh (1 term).
// exp without max-subtraction; P packed to fp16 A-frags in registers;
// O in regs. cp.async 2-stage K/V (hi only); 2 CTAs/SM.
// smem bytes (row pitch 144): Qh 0, Ql 9216,
//   stage s at 18432+s*18432: Kh +0, Vh +9216. Total 55296.
// ---------------------------------------------------------------------------
#define ASTG 18432
__global__ __launch_bounds__(256, 2) void attn(float* __restrict__ out) {
    extern __shared__ __align__(16) unsigned char sm_raw[];
    const unsigned sb = smem_u32(sm_raw);
    const int tid = threadIdx.x, lane = tid & 31, wid = tid >> 5;
    const int g = wid & 3, js = wid >> 2;
    const int b = blockIdx.z, h = blockIdx.y, q0 = blockIdx.x * 64;

    const int krow = tid >> 2, kq = (tid & 3) * 16;
    const size_t kvb = (size_t)(b * NSEQ + krow) * QKVS + h * 64 + kq;
    const unsigned kvd = (unsigned)((krow * 72 + kq) * 2);
    auto issue_kv = [&](int t, int s) {
        const unsigned st = sb + 18432 + s * ASTG + kvd;
        const size_t r = kvb + (size_t)t * 64 * QKVS;
        CPA(st,         g_sh + r + DIMX);      CPA(st + 16,        g_sh + r + DIMX + 8);
        CPA(st + 9216,  g_sh + r + 2 * DIMX);  CPA(st + 9216 + 16, g_sh + r + 2 * DIMX + 8);
        CPA_COMMIT();
    };
    issue_kv(0, 0);
    issue_kv(1, 1);

    // Q tile (64 rows, hi/lo) via plain LDG/STS (once)
    {
        size_t go = (size_t)(b * NSEQ + q0 + krow) * QKVS + h * 64 + kq;
        *(uint4*)(sm_raw + kvd)             = *(const uint4*)(g_sh + go);
        *(uint4*)(sm_raw + kvd + 16)        = *(const uint4*)(g_sh + go + 8);
        *(uint4*)(sm_raw + 9216 + kvd)      = *(const uint4*)(g_sl + go);
        *(uint4*)(sm_raw + 9216 + kvd + 16) = *(const uint4*)(g_sl + go + 8);
    }
    __syncthreads();

    // persistent Q frags (hi + lo)
    const unsigned qA = sb + (unsigned)((g * 16 + (lane & 15)) * 144 + (lane >> 4) * 16);
    unsigned qfh[4][4], qfl[4][4];
#pragma unroll
    for (int s = 0; s < 4; s++) {
        ldsm4(qfh[s], qA + s * 32);
        ldsm4(qfl[s], qA + 9216 + s * 32);
    }

    float o[8][4];
#pragma unroll
    for (int i = 0; i < 8; i++)
#pragma unroll
        for (int q = 0; q < 4; q++) o[i][q] = 0.f;
    float l0 = 0.f, l1 = 0.f;

    const unsigned kOff = (unsigned)((js * 32 + (lane & 7) + ((lane >> 4) << 3)) * 144 +
                                     ((lane >> 3) & 1) * 16);
    const unsigned vOff = 9216 + (unsigned)(((lane & 15)) * 144 + (lane >> 4) * 16);
    const int r0 = g * 16 + (lane >> 2);

    for (int t = 0; t < 32; t++) {
        cpa_wait<1>();
        __syncthreads();
        const unsigned st = sb + 18432 + (t & 1) * ASTG;
        const unsigned khA = st + kOff, vhA = st + vOff;

        // ---- S = Q K^T (q 2-term, k 1-term) ----
        float sacc[4][4];
#pragma unroll
        for (int jt = 0; jt < 4; jt++)
#pragma unroll
            for (int q = 0; q < 4; q++) sacc[jt][q] = 0.f;
#pragma unroll
        for (int s = 0; s < 4; s++) {
            unsigned kh0[4], kh1[4];
            ldsm4(kh0, khA + s * 32);
            ldsm4(kh1, khA + 2304 + s * 32);
            mmah(sacc[0], qfh[s], kh0[0], kh0[1]);
            mmah(sacc[0], qfl[s], kh0[0], kh0[1]);
            mmah(sacc[1], qfh[s], kh0[2], kh0[3]);
            mmah(sacc[1], qfl[s], kh0[2], kh0[3]);
            mmah(sacc[2], qfh[s], kh1[0], kh1[1]);
            mmah(sacc[2], qfl[s], kh1[0], kh1[1]);
            mmah(sacc[3], qfh[s], kh1[2], kh1[3]);
            mmah(sacc[3], qfl[s], kh1[2], kh1[3]);
        }

        // ---- softmax (no max shift), P packed to fp16 A-frags (1-term) ----
        unsigned aP[2][4];
#pragma unroll
        for (int jt = 0; jt < 4; jt++) {
            float p0 = __expf(sacc[jt][0]), p1 = __expf(sacc[jt][1]);
            float p2 = __expf(sacc[jt][2]), p3 = __expf(sacc[jt][3]);
            l0 += p0 + p1;
            l1 += p2 + p3;
            aP[jt >> 1][(jt & 1) * 2 + 0] = u32h(__floats2half2_rn(p0, p1));
            aP[jt >> 1][(jt & 1) * 2 + 1] = u32h(__floats2half2_rn(p2, p3));
        }

        // ---- O += P V (V via ldmatrix.trans; k offset = js half) ----
#pragma unroll
        for (int sp = 0; sp < 2; sp++) {
            const unsigned vk = (js * 32 + sp * 16) * 144;
#pragma unroll
            for (int db = 0; db < 4; db++) {
                unsigned vh[4];
                ldsm4t(vh, vhA + vk + db * 32);
                mmah(o[2 * db + 0], aP[sp], vh[0], vh[1]);
                mmah(o[2 * db + 1], aP[sp], vh[2], vh[3]);
            }
        }
        __syncthreads();
        if (t + 2 < 32) issue_kv(t + 2, t & 1);
    }

    // ---- reduce l across quad ----
    l0 += __shfl_xor_sync(0xffffffffu, l0, 1);
    l0 += __shfl_xor_sync(0xffffffffu, l0, 2);
    l1 += __shfl_xor_sync(0xffffffffu, l1, 1);
    l1 += __shfl_xor_sync(0xffffffffu, l1, 2);

    // ---- cross-half (js) reduction via smem float scratch (reuses Q) ----
    float* red = (float*)sm_raw;                      // [64][68]
    float* redl = (float*)(sm_raw + 64 * 68 * 4);     // [64]
    if (js == 1) {
#pragma unroll
        for (int dt = 0; dt < 8; dt++) {
            *(float2*)&red[r0 * 68 + dt * 8 + (lane & 3) * 2] = make_float2(o[dt][0], o[dt][1]);
            *(float2*)&red[(r0 + 8) * 68 + dt * 8 + (lane & 3) * 2] = make_float2(o[dt][2], o[dt][3]);
        }
        if ((lane & 3) == 0) { redl[r0] = l0; redl[r0 + 8] = l1; }
    }
    __syncthreads();
    if (js == 0) {
        float inv0 = 1.f / (l0 + redl[r0]);
        float inv1 = 1.f / (l1 + redl[r0 + 8]);
        float* op0 = out + ((size_t)(b * NSEQ + q0 + r0) * HH + h) * DD;
        float* op1 = out + ((size_t)(b * NSEQ + q0 + r0 + 8) * HH + h) * DD;
#pragma unroll
        for (int dt = 0; dt < 8; dt++) {
            float2 e0 = *(const float2*)&red[r0 * 68 + dt * 8 + (lane & 3) * 2];
            float2 e1 = *(const float2*)&red[(r0 + 8) * 68 + dt * 8 + (lane & 3) * 2];
            *(float2*)&op0[dt * 8 + (lane & 3) * 2] =
                make_float2((o[dt][0] + e0.x) * inv0, (o[dt][1] + e0.y) * inv0);
            *(float2*)&op1[dt * 8 + (lane & 3) * 2] =
                make_float2((o[dt][2] + e1.x) * inv1, (o[dt][3] + e1.y) * inv1);
        }
    }
}

// ---------------------------------------------------------------------------
extern "C" void kernel_launch(void* const* d_in, const int* in_sizes, int n_in,
                              void* d_out, int out_size) {
    (void)in_sizes; (void)n_in; (void)out_size;
    const float* x = (const float*)d_in[0];
    const float* w = (const float*)d_in[1];
    float* out = (float*)d_out;

    __half *xh, *xl, *wh;
    cudaGetSymbolAddress((void**)&xh, g_xh);
    cudaGetSymbolAddress((void**)&xl, g_xl);
    cudaGetSymbolAddress((void**)&wh, g_wh);

    const int gemm_smem = 3 * GSTG;                 // 92160
    const int attn_smem = 18432 + 2 * ASTG;         // 55296
    cudaFuncSetAttribute((const void*)qkv_gemm,
                         cudaFuncAttributeMaxDynamicSharedMemorySize, gemm_smem);
    cudaFuncSetAttribute((const void*)attn,
                         cudaFuncAttributeMaxDynamicSharedMemorySize, attn_smem);

    split_hl<<<(GM * GK / 4 + 255) / 256, 256>>>(x, xh, xl, GM * GK / 4);
    split_h<<<(GN * GK / 4 + 255) / 256, 256>>>(w, wh, GN * GK / 4);

    dim3 g1(GN / 128, GM / 128);           // (24, 32)
    qkv_gemm<<<g1, 256, gemm_smem>>>();

    dim3 g2(NSEQ / 64, HH, BB);            // (32, 16, 2)
    attn<<<g2, 256, attn_smem>>>(out);
}

// round 9
// speedup vs baseline: 1.8505x; 1.0605x over previous
#include <cuda_runtime.h>
#include <cuda_fp16.h>

#define BB    2
#define NSEQ  2048
#define DIMX  1024
#define HH    16
#define DD    64
#define QKVS  3072
#define GM    4096
#define GN    3072
#define GK    1024

// fp16 hi/lo split scratch (precomputed inputs + QKV projection output)
__device__ __half g_xh[(size_t)GM * GK], g_xl[(size_t)GM * GK];
__device__ __half g_wh[(size_t)GN * GK];
__device__ __half g_sh[(size_t)GM * GN], g_sl[(size_t)GM * GN];

// ---------------------------------------------------------------------------
// portable PTX helpers (sm_80 feature set only)
// ---------------------------------------------------------------------------
__device__ __forceinline__ unsigned smem_u32(const void* p) {
    unsigned a;
    asm("{ .reg .u64 t; cvta.to.shared.u64 t, %1; cvt.u32.u64 %0, t; }" : "=r"(a) : "l"(p));
    return a;
}
__device__ __forceinline__ void ldsm4(unsigned* r, unsigned a) {
    asm volatile("ldmatrix.sync.aligned.m8n8.x4.shared.b16 {%0,%1,%2,%3}, [%4];"
                 : "=r"(r[0]), "=r"(r[1]), "=r"(r[2]), "=r"(r[3]) : "r"(a));
}
__device__ __forceinline__ void ldsm4t(unsigned* r, unsigned a) {
    asm volatile("ldmatrix.sync.aligned.m8n8.x4.trans.shared.b16 {%0,%1,%2,%3}, [%4];"
                 : "=r"(r[0]), "=r"(r[1]), "=r"(r[2]), "=r"(r[3]) : "r"(a));
}
__device__ __forceinline__ void mmah(float* c, const unsigned* a, unsigned b0, unsigned b1) {
    asm volatile("mma.sync.aligned.m16n8k16.row.col.f32.f16.f16.f32 "
                 "{%0,%1,%2,%3}, {%4,%5,%6,%7}, {%8,%9}, {%0,%1,%2,%3};"
                 : "+f"(c[0]), "+f"(c[1]), "+f"(c[2]), "+f"(c[3])
                 : "r"(a[0]), "r"(a[1]), "r"(a[2]), "r"(a[3]), "r"(b0), "r"(b1));
}
__device__ __forceinline__ void split2h(float a, float b, __half2& h, __half2& l) {
    h = __floats2half2_rn(a, b);
    l = __floats2half2_rn(a - __low2float(h), b - __high2float(h));
}
__device__ __forceinline__ unsigned u32h(__half2 v) { return *(unsigned*)&v; }
#define CPA(dst, src) \
    asm volatile("cp.async.cg.shared.global [%0], [%1], 16;" :: "r"(dst), "l"(src))
#define CPA_COMMIT() asm volatile("cp.async.commit_group;" ::: "memory")
template <int N>
__device__ __forceinline__ void cpa_wait() {
    asm volatile("cp.async.wait_group %0;" :: "n"(N) : "memory");
}

// ---------------------------------------------------------------------------
// Kernel 0a: fp32 -> fp16 hi/lo split
// ---------------------------------------------------------------------------
__global__ __launch_bounds__(256) void split_hl(const float* __restrict__ src,
                                                __half* __restrict__ hi,
                                                __half* __restrict__ lo, int n4) {
    int i = blockIdx.x * 256 + threadIdx.x;
    if (i >= n4) return;
    float4 v = ((const float4*)src)[i];
    __half2 h0, l0, h1, l1;
    split2h(v.x, v.y, h0, l0);
    split2h(v.z, v.w, h1, l1);
    ((__half2*)hi)[i * 2 + 0] = h0;
    ((__half2*)hi)[i * 2 + 1] = h1;
    ((__half2*)lo)[i * 2 + 0] = l0;
    ((__half2*)lo)[i * 2 + 1] = l1;
}
// Kernel 0b: fp32 -> fp16 (1-term, for w)
__global__ __launch_bounds__(256) void split_h(const float* __restrict__ src,
                                               __half* __restrict__ hi, int n4) {
    int i = blockIdx.x * 256 + threadIdx.x;
    if (i >= n4) return;
    float4 v = ((const float4*)src)[i];
    ((__half2*)hi)[i * 2 + 0] = __floats2half2_rn(v.x, v.y);
    ((__half2*)hi)[i * 2 + 1] = __floats2half2_rn(v.z, v.w);
}

// ---------------------------------------------------------------------------
// Kernel 1: QKV GEMM, fp16 2-term (xh*wh + xl*wh), cp.async 3-stage ring.
// CTA 128x128, K-chunk 32. 8 warps = 4(m) x 2(n), warp tile 32x64.
// Stage (30720 B): Ah 0, Al 10240, Bh 20480; pitch 80 B. 2 CTAs/SM.
// Inner loop: full hi-sweep (16 mma) then lo-sweep (16 mma) per k-step ->
// accumulator reuse distance 16 (was 1).
// ---------------------------------------------------------------------------
#define GSTG 30720
__global__ __launch_bounds__(256, 2) void qkv_gemm() {
    extern __shared__ __align__(16) unsigned char gs[];
    const unsigned sb = smem_u32(gs);
    const int tid = threadIdx.x, lane = tid & 31, wid = tid >> 5;
    const int wm = wid & 3, wn = wid >> 2;
    const int bm = blockIdx.y * 128, bn = blockIdx.x * 128;

    float acc[2][8][4];
#pragma unroll
    for (int i = 0; i < 2; i++)
#pragma unroll
        for (int j = 0; j < 8; j++)
#pragma unroll
            for (int q = 0; q < 4; q++) acc[i][j][q] = 0.f;

    const int lrow = tid >> 1, lh = (tid & 1) * 16;
    const __half* xh = g_xh + (size_t)(bm + lrow) * GK + lh;
    const __half* xl = g_xl + (size_t)(bm + lrow) * GK + lh;
    const __half* wh = g_wh + (size_t)(bn + lrow) * GK + lh;
    const unsigned drow = lrow * 80 + lh * 2;

    auto issue = [&](int c, int s) {
        const unsigned st = sb + s * GSTG + drow;
        const int ko = c * 32;
        CPA(st,             xh + ko);  CPA(st + 16,         xh + ko + 8);
        CPA(st + 10240,     xl + ko);  CPA(st + 10240 + 16, xl + ko + 8);
        CPA(st + 20480,     wh + ko);  CPA(st + 20480 + 16, wh + ko + 8);
        CPA_COMMIT();
    };

    const unsigned aOff = (unsigned)((wm * 32 + (lane & 15)) * 80 + (lane >> 4) * 16);
    const unsigned bOff = 20480 + (unsigned)((wn * 64 + (lane & 7) + ((lane >> 4) << 3)) * 80 +
                                             ((lane >> 3) & 1) * 16);

    issue(0, 0);
    issue(1, 1);
    int stg = 0;
    for (int c = 0; c < 32; c++) {
        cpa_wait<1>();
        __syncthreads();
        if (c + 2 < 32) {
            int s2 = stg + 2; if (s2 >= 3) s2 -= 3;
            issue(c + 2, s2);
        }
        const unsigned st = sb + stg * GSTG;
        if (++stg == 3) stg = 0;
        const unsigned aAddr = st + aOff, bAddr = st + bOff;
#pragma unroll
        for (int s = 0; s < 2; s++) {
            unsigned ah[2][4], al[2][4], bh[4][4];
            ldsm4(ah[0], aAddr + s * 32);
            ldsm4(ah[1], aAddr + 1280 + s * 32);
            ldsm4(al[0], aAddr + 10240 + s * 32);
            ldsm4(al[1], aAddr + 10240 + 1280 + s * 32);
#pragma unroll
            for (int np = 0; np < 4; np++) ldsm4(bh[np], bAddr + np * 1280 + s * 32);
            // hi sweep: 16 mma, all distinct accumulators
#pragma unroll
            for (int np = 0; np < 4; np++)
#pragma unroll
                for (int mt = 0; mt < 2; mt++) {
                    mmah(acc[mt][2 * np + 0], ah[mt], bh[np][0], bh[np][1]);
                    mmah(acc[mt][2 * np + 1], ah[mt], bh[np][2], bh[np][3]);
                }
            // lo sweep: 16 mma
#pragma unroll
            for (int np = 0; np < 4; np++)
#pragma unroll
                for (int mt = 0; mt < 2; mt++) {
                    mmah(acc[mt][2 * np + 0], al[mt], bh[np][0], bh[np][1]);
                    mmah(acc[mt][2 * np + 1], al[mt], bh[np][2], bh[np][3]);
                }
        }
    }

#pragma unroll
    for (int mt = 0; mt < 2; mt++) {
        int m = bm + wm * 32 + mt * 16 + (lane >> 2);
#pragma unroll
        for (int nt = 0; nt < 8; nt++) {
            int gc = bn + wn * 64 + nt * 8 + ((lane & 3) << 1);
            float sc = (gc < DIMX) ? 0.125f : 1.0f;
            __half2 h, l;
            split2h(acc[mt][nt][0] * sc, acc[mt][nt][1] * sc, h, l);
            *(__half2*)(g_sh + (size_t)m * GN + gc) = h;
            *(__half2*)(g_sl + (size_t)m * GN + gc) = l;
            split2h(acc[mt][nt][2] * sc, acc[mt][nt][3] * sc, h, l);
            *(__half2*)(g_sh + (size_t)(m + 8) * GN + gc) = h;
            *(__half2*)(g_sl + (size_t)(m + 8) * GN + gc) = l;
        }
    }
}

// ---------------------------------------------------------------------------
// Kernel 2: attention. CTA = (b, h, 64 Q rows); 8 warps = 4 row-groups(16) x
// 2 j-halves(32). S = (qh+ql)*kh (hi sweep then lo sweep), PV = P*vh.
// exp without max-subtraction; P packed to fp16 A-frags in registers;
// O in regs. cp.async 3-stage K/V ring (ONE sync/tile); 2 CTAs/SM.
// smem bytes (row pitch 144): Qh 0, Ql 9216,
//   stage s at 18432+s*18432: Kh +0, Vh +9216. Total 73728.
// ---------------------------------------------------------------------------
#define ASTG 18432
__global__ __launch_bounds__(256, 2) void attn(float* __restrict__ out) {
    extern __shared__ __align__(16) unsigned char sm_raw[];
    const unsigned sb = smem_u32(sm_raw);
    const int tid = threadIdx.x, lane = tid & 31, wid = tid >> 5;
    const int g = wid & 3, js = wid >> 2;
    const int b = blockIdx.z, h = blockIdx.y, q0 = blockIdx.x * 64;

    const int krow = tid >> 2, kq = (tid & 3) * 16;
    const size_t kvb = (size_t)(b * NSEQ + krow) * QKVS + h * 64 + kq;
    const unsigned kvd = (unsigned)((krow * 72 + kq) * 2);
    auto issue_kv = [&](int t, int s) {
        const unsigned st = sb + 18432 + s * ASTG + kvd;
        const size_t r = kvb + (size_t)t * 64 * QKVS;
        CPA(st,         g_sh + r + DIMX);      CPA(st + 16,        g_sh + r + DIMX + 8);
        CPA(st + 9216,  g_sh + r + 2 * DIMX);  CPA(st + 9216 + 16, g_sh + r + 2 * DIMX + 8);
        CPA_COMMIT();
    };
    issue_kv(0, 0);
    issue_kv(1, 1);

    // Q tile (64 rows, hi/lo) via plain LDG/STS (once)
    {
        size_t go = (size_t)(b * NSEQ + q0 + krow) * QKVS + h * 64 + kq;
        *(uint4*)(sm_raw + kvd)             = *(const uint4*)(g_sh + go);
        *(uint4*)(sm_raw + kvd + 16)        = *(const uint4*)(g_sh + go + 8);
        *(uint4*)(sm_raw + 9216 + kvd)      = *(const uint4*)(g_sl + go);
        *(uint4*)(sm_raw + 9216 + kvd + 16) = *(const uint4*)(g_sl + go + 8);
    }
    __syncthreads();

    // persistent Q frags (hi + lo)
    const unsigned qA = sb + (unsigned)((g * 16 + (lane & 15)) * 144 + (lane >> 4) * 16);
    unsigned qfh[4][4], qfl[4][4];
#pragma unroll
    for (int s = 0; s < 4; s++) {
        ldsm4(qfh[s], qA + s * 32);
        ldsm4(qfl[s], qA + 9216 + s * 32);
    }

    float o[8][4];
#pragma unroll
    for (int i = 0; i < 8; i++)
#pragma unroll
        for (int q = 0; q < 4; q++) o[i][q] = 0.f;
    float l0 = 0.f, l1 = 0.f;

    const unsigned kOff = (unsigned)((js * 32 + (lane & 7) + ((lane >> 4) << 3)) * 144 +
                                     ((lane >> 3) & 1) * 16);
    const unsigned vOff = 9216 + (unsigned)(((lane & 15)) * 144 + (lane >> 4) * 16);
    const int r0 = g * 16 + (lane >> 2);

    int stg = 0;
    for (int t = 0; t < 32; t++) {
        cpa_wait<1>();
        __syncthreads();
        if (t + 2 < 32) {
            int s2 = stg + 2; if (s2 >= 3) s2 -= 3;
            issue_kv(t + 2, s2);
        }
        const unsigned st = sb + 18432 + stg * ASTG;
        if (++stg == 3) stg = 0;
        const unsigned khA = st + kOff, vhA = st + vOff;

        // ---- S = Q K^T (hi sweep over 4 tiles, then lo sweep) ----
        float sacc[4][4];
#pragma unroll
        for (int jt = 0; jt < 4; jt++)
#pragma unroll
            for (int q = 0; q < 4; q++) sacc[jt][q] = 0.f;
#pragma unroll
        for (int s = 0; s < 4; s++) {
            unsigned kh0[4], kh1[4];
            ldsm4(kh0, khA + s * 32);
            ldsm4(kh1, khA + 2304 + s * 32);
            mmah(sacc[0], qfh[s], kh0[0], kh0[1]);
            mmah(sacc[1], qfh[s], kh0[2], kh0[3]);
            mmah(sacc[2], qfh[s], kh1[0], kh1[1]);
            mmah(sacc[3], qfh[s], kh1[2], kh1[3]);
            mmah(sacc[0], qfl[s], kh0[0], kh0[1]);
            mmah(sacc[1], qfl[s], kh0[2], kh0[3]);
            mmah(sacc[2], qfl[s], kh1[0], kh1[1]);
            mmah(sacc[3], qfl[s], kh1[2], kh1[3]);
        }

        // ---- softmax (no max shift), P packed to fp16 A-frags ----
        unsigned aP[2][4];
#pragma unroll
        for (int jt = 0; jt < 4; jt++) {
            float p0 = __expf(sacc[jt][0]), p1 = __expf(sacc[jt][1]);
            float p2 = __expf(sacc[jt][2]), p3 = __expf(sacc[jt][3]);
            l0 += p0 + p1;
            l1 += p2 + p3;
            aP[jt >> 1][(jt & 1) * 2 + 0] = u32h(__floats2half2_rn(p0, p1));
            aP[jt >> 1][(jt & 1) * 2 + 1] = u32h(__floats2half2_rn(p2, p3));
        }

        // ---- O += P V (V via ldmatrix.trans; k offset = js half) ----
#pragma unroll
        for (int sp = 0; sp < 2; sp++) {
            const unsigned vk = (js * 32 + sp * 16) * 144;
#pragma unroll
            for (int db = 0; db < 4; db++) {
                unsigned vh[4];
                ldsm4t(vh, vhA + vk + db * 32);
                mmah(o[2 * db + 0], aP[sp], vh[0], vh[1]);
                mmah(o[2 * db + 1], aP[sp], vh[2], vh[3]);
            }
        }
    }

    // ---- reduce l across quad ----
    l0 += __shfl_xor_sync(0xffffffffu, l0, 1);
    l0 += __shfl_xor_sync(0xffffffffu, l0, 2);
    l1 += __shfl_xor_sync(0xffffffffu, l1, 1);
    l1 += __shfl_xor_sync(0xffffffffu, l1, 2);

    // ---- cross-half (js) reduction via smem float scratch (reuses Q) ----
    __syncthreads();
    float* red = (float*)sm_raw;                      // [64][68]
    float* redl = (float*)(sm_raw + 64 * 68 * 4);     // [64]
    if (js == 1) {
#pragma unroll
        for (int dt = 0; dt < 8; dt++) {
            *(float2*)&red[r0 * 68 + dt * 8 + (lane & 3) * 2] = make_float2(o[dt][0], o[dt][1]);
            *(float2*)&red[(r0 + 8) * 68 + dt * 8 + (lane & 3) * 2] = make_float2(o[dt][2], o[dt][3]);
        }
        if ((lane & 3) == 0) { redl[r0] = l0; redl[r0 + 8] = l1; }
    }
    __syncthreads();
    if (js == 0) {
        float inv0 = 1.f / (l0 + redl[r0]);
        float inv1 = 1.f / (l1 + redl[r0 + 8]);
        float* op0 = out + ((size_t)(b * NSEQ + q0 + r0) * HH + h) * DD;
        float* op1 = out + ((size_t)(b * NSEQ + q0 + r0 + 8) * HH + h) * DD;
#pragma unroll
        for (int dt = 0; dt < 8; dt++) {
            float2 e0 = *(const float2*)&red[r0 * 68 + dt * 8 + (lane & 3) * 2];
            float2 e1 = *(const float2*)&red[(r0 + 8) * 68 + dt * 8 + (lane & 3) * 2];
            *(float2*)&op0[dt * 8 + (lane & 3) * 2] =
                make_float2((o[dt][0] + e0.x) * inv0, (o[dt][1] + e0.y) * inv0);
            *(float2*)&op1[dt * 8 + (lane & 3) * 2] =
                make_float2((o[dt][2] + e1.x) * inv1, (o[dt][3] + e1.y) * inv1);
        }
    }
}

// ---------------------------------------------------------------------------
extern "C" void kernel_launch(void* const* d_in, const int* in_sizes, int n_in,
                              void* d_out, int out_size) {
    (void)in_sizes; (void)n_in; (void)out_size;
    const float* x = (const float*)d_in[0];
    const float* w = (const float*)d_in[1];
    float* out = (float*)d_out;

    __half *xh, *xl, *wh;
    cudaGetSymbolAddress((void**)&xh, g_xh);
    cudaGetSymbolAddress((void**)&xl, g_xl);
    cudaGetSymbolAddress((void**)&wh, g_wh);

    const int gemm_smem = 3 * GSTG;                 // 92160
    const int attn_smem = 18432 + 3 * ASTG;         // 73728
    cudaFuncSetAttribute((const void*)qkv_gemm,
                         cudaFuncAttributeMaxDynamicSharedMemorySize, gemm_smem);
    cudaFuncSetAttribute((const void*)attn,
                         cudaFuncAttributeMaxDynamicSharedMemorySize, attn_smem);

    split_hl<<<(GM * GK / 4 + 255) / 256, 256>>>(x, xh, xl, GM * GK / 4);
    split_h<<<(GN * GK / 4 + 255) / 256, 256>>>(w, wh, GN * GK / 4);

    dim3 g1(GN / 128, GM / 128);           // (24, 32)
    qkv_gemm<<<g1, 256, gemm_smem>>>();

    dim3 g2(NSEQ / 64, HH, BB);            // (32, 16, 2)
    attn<<<g2, 256, attn_smem>>>(out);
}

// round 10
// speedup vs baseline: 2.0493x; 1.1074x over previous
#include <cuda_runtime.h>
#include <cuda_fp16.h>

#define BB    2
#define NSEQ  2048
#define DIMX  1024
#define HH    16
#define DD    64
#define QKVS  3072
#define GM    4096
#define GN    3072
#define GK    1024

// fp16 scratch: x hi/lo split, w 1-term, QKV projection output (1-term)
__device__ __half g_xh[(size_t)GM * GK], g_xl[(size_t)GM * GK];
__device__ __half g_wh[(size_t)GN * GK];
__device__ __half g_sh[(size_t)GM * GN];

// ---------------------------------------------------------------------------
// portable PTX helpers (sm_80 feature set only)
// ---------------------------------------------------------------------------
__device__ __forceinline__ unsigned smem_u32(const void* p) {
    unsigned a;
    asm("{ .reg .u64 t; cvta.to.shared.u64 t, %1; cvt.u32.u64 %0, t; }" : "=r"(a) : "l"(p));
    return a;
}
__device__ __forceinline__ void ldsm4(unsigned* r, unsigned a) {
    asm volatile("ldmatrix.sync.aligned.m8n8.x4.shared.b16 {%0,%1,%2,%3}, [%4];"
                 : "=r"(r[0]), "=r"(r[1]), "=r"(r[2]), "=r"(r[3]) : "r"(a));
}
__device__ __forceinline__ void ldsm4t(unsigned* r, unsigned a) {
    asm volatile("ldmatrix.sync.aligned.m8n8.x4.trans.shared.b16 {%0,%1,%2,%3}, [%4];"
                 : "=r"(r[0]), "=r"(r[1]), "=r"(r[2]), "=r"(r[3]) : "r"(a));
}
__device__ __forceinline__ void mmah(float* c, const unsigned* a, unsigned b0, unsigned b1) {
    asm volatile("mma.sync.aligned.m16n8k16.row.col.f32.f16.f16.f32 "
                 "{%0,%1,%2,%3}, {%4,%5,%6,%7}, {%8,%9}, {%0,%1,%2,%3};"
                 : "+f"(c[0]), "+f"(c[1]), "+f"(c[2]), "+f"(c[3])
                 : "r"(a[0]), "r"(a[1]), "r"(a[2]), "r"(a[3]), "r"(b0), "r"(b1));
}
__device__ __forceinline__ void split2h(float a, float b, __half2& h, __half2& l) {
    h = __floats2half2_rn(a, b);
    l = __floats2half2_rn(a - __low2float(h), b - __high2float(h));
}
__device__ __forceinline__ unsigned u32h(__half2 v) { return *(unsigned*)&v; }
__device__ __forceinline__ float ex2(float x) {
    float y;
    asm("ex2.approx.f32 %0, %1;" : "=f"(y) : "f"(x));
    return y;
}
#define CPA(dst, src) \
    asm volatile("cp.async.cg.shared.global [%0], [%1], 16;" :: "r"(dst), "l"(src))
#define CPA_COMMIT() asm volatile("cp.async.commit_group;" ::: "memory")
template <int N>
__device__ __forceinline__ void cpa_wait() {
    asm volatile("cp.async.wait_group %0;" :: "n"(N) : "memory");
}

// ---------------------------------------------------------------------------
// Kernel 0a: fp32 -> fp16 hi/lo split (x)
// ---------------------------------------------------------------------------
__global__ __launch_bounds__(256) void split_hl(const float* __restrict__ src,
                                                __half* __restrict__ hi,
                                                __half* __restrict__ lo, int n4) {
    int i = blockIdx.x * 256 + threadIdx.x;
    if (i >= n4) return;
    float4 v = ((const float4*)src)[i];
    __half2 h0, l0, h1, l1;
    split2h(v.x, v.y, h0, l0);
    split2h(v.z, v.w, h1, l1);
    ((__half2*)hi)[i * 2 + 0] = h0;
    ((__half2*)hi)[i * 2 + 1] = h1;
    ((__half2*)lo)[i * 2 + 0] = l0;
    ((__half2*)lo)[i * 2 + 1] = l1;
}
// Kernel 0b: fp32 -> fp16 (1-term, w)
__global__ __launch_bounds__(256) void split_h(const float* __restrict__ src,
                                               __half* __restrict__ hi, int n4) {
    int i = blockIdx.x * 256 + threadIdx.x;
    if (i >= n4) return;
    float4 v = ((const float4*)src)[i];
    ((__half2*)hi)[i * 2 + 0] = __floats2half2_rn(v.x, v.y);
    ((__half2*)hi)[i * 2 + 1] = __floats2half2_rn(v.z, v.w);
}

// ---------------------------------------------------------------------------
// Kernel 1: QKV GEMM, fp16 2-term (xh*wh + xl*wh), cp.async 3-stage ring.
// CTA 128x128, K-chunk 32. 8 warps = 4(m) x 2(n), warp tile 32x64.
// Stage (30720 B): Ah 0, Al 10240, Bh 20480; pitch 80 B. 2 CTAs/SM.
// Epilogue: 1-term fp16 store; Q region scaled by 0.125/ln2 (for ex2 softmax).
// ---------------------------------------------------------------------------
#define GSTG 30720
#define QSCALE 0.18033688f   // 0.125 / ln(2)
__global__ __launch_bounds__(256, 2) void qkv_gemm() {
    extern __shared__ __align__(16) unsigned char gs[];
    const unsigned sb = smem_u32(gs);
    const int tid = threadIdx.x, lane = tid & 31, wid = tid >> 5;
    const int wm = wid & 3, wn = wid >> 2;
    const int bm = blockIdx.y * 128, bn = blockIdx.x * 128;

    float acc[2][8][4];
#pragma unroll
    for (int i = 0; i < 2; i++)
#pragma unroll
        for (int j = 0; j < 8; j++)
#pragma unroll
            for (int q = 0; q < 4; q++) acc[i][j][q] = 0.f;

    const int lrow = tid >> 1, lh = (tid & 1) * 16;
    const __half* xh = g_xh + (size_t)(bm + lrow) * GK + lh;
    const __half* xl = g_xl + (size_t)(bm + lrow) * GK + lh;
    const __half* wh = g_wh + (size_t)(bn + lrow) * GK + lh;
    const unsigned drow = lrow * 80 + lh * 2;

    auto issue = [&](int c, int s) {
        const unsigned st = sb + s * GSTG + drow;
        const int ko = c * 32;
        CPA(st,             xh + ko);  CPA(st + 16,         xh + ko + 8);
        CPA(st + 10240,     xl + ko);  CPA(st + 10240 + 16, xl + ko + 8);
        CPA(st + 20480,     wh + ko);  CPA(st + 20480 + 16, wh + ko + 8);
        CPA_COMMIT();
    };

    const unsigned aOff = (unsigned)((wm * 32 + (lane & 15)) * 80 + (lane >> 4) * 16);
    const unsigned bOff = 20480 + (unsigned)((wn * 64 + (lane & 7) + ((lane >> 4) << 3)) * 80 +
                                             ((lane >> 3) & 1) * 16);

    issue(0, 0);
    issue(1, 1);
    int stg = 0;
    for (int c = 0; c < 32; c++) {
        cpa_wait<1>();
        __syncthreads();
        if (c + 2 < 32) {
            int s2 = stg + 2; if (s2 >= 3) s2 -= 3;
            issue(c + 2, s2);
        }
        const unsigned st = sb + stg * GSTG;
        if (++stg == 3) stg = 0;
        const unsigned aAddr = st + aOff, bAddr = st + bOff;
#pragma unroll
        for (int s = 0; s < 2; s++) {
            unsigned ah[2][4], al[2][4], bh[4][4];
            ldsm4(ah[0], aAddr + s * 32);
            ldsm4(ah[1], aAddr + 1280 + s * 32);
            ldsm4(al[0], aAddr + 10240 + s * 32);
            ldsm4(al[1], aAddr + 10240 + 1280 + s * 32);
#pragma unroll
            for (int np = 0; np < 4; np++) ldsm4(bh[np], bAddr + np * 1280 + s * 32);
#pragma unroll
            for (int np = 0; np < 4; np++)
#pragma unroll
                for (int mt = 0; mt < 2; mt++) {
                    mmah(acc[mt][2 * np + 0], ah[mt], bh[np][0], bh[np][1]);
                    mmah(acc[mt][2 * np + 1], ah[mt], bh[np][2], bh[np][3]);
                }
#pragma unroll
            for (int np = 0; np < 4; np++)
#pragma unroll
                for (int mt = 0; mt < 2; mt++) {
                    mmah(acc[mt][2 * np + 0], al[mt], bh[np][0], bh[np][1]);
                    mmah(acc[mt][2 * np + 1], al[mt], bh[np][2], bh[np][3]);
                }
        }
    }

#pragma unroll
    for (int mt = 0; mt < 2; mt++) {
        int m = bm + wm * 32 + mt * 16 + (lane >> 2);
#pragma unroll
        for (int nt = 0; nt < 8; nt++) {
            int gc = bn + wn * 64 + nt * 8 + ((lane & 3) << 1);
            float sc = (gc < DIMX) ? QSCALE : 1.0f;
            *(__half2*)(g_sh + (size_t)m * GN + gc) =
                __floats2half2_rn(acc[mt][nt][0] * sc, acc[mt][nt][1] * sc);
            *(__half2*)(g_sh + (size_t)(m + 8) * GN + gc) =
                __floats2half2_rn(acc[mt][nt][2] * sc, acc[mt][nt][3] * sc);
        }
    }
}

// ---------------------------------------------------------------------------
// Kernel 2: attention. CTA = (b, h, 64 Q rows); 8 warps = 4 row-groups(16) x
// 2 j-halves(32). 1-term fp16 everywhere (error suppressed by softmax
// averaging). Software-pipelined: S(t+1) interleaved with PV(t) so the
// tensor pipe streams through the softmax. ex2-based softmax (scale folded
// upstream). cp.async 4-stage K/V ring; ONE sync/tile; 2 CTAs/SM.
// smem bytes (row pitch 144): Qh 0..9216,
//   stage s at 9216+s*18432: Kh +0, Vh +9216. Total 82944.
// ---------------------------------------------------------------------------
#define ASTG 18432
__global__ __launch_bounds__(256, 2) void attn(float* __restrict__ out) {
    extern __shared__ __align__(16) unsigned char sm_raw[];
    const unsigned sb = smem_u32(sm_raw);
    const int tid = threadIdx.x, lane = tid & 31, wid = tid >> 5;
    const int g = wid & 3, js = wid >> 2;
    const int b = blockIdx.z, h = blockIdx.y, q0 = blockIdx.x * 64;

    const int krow = tid >> 2, kq = (tid & 3) * 16;
    const size_t kvb = (size_t)(b * NSEQ + krow) * QKVS + h * 64 + kq;
    const unsigned kvd = (unsigned)((krow * 72 + kq) * 2);
    auto issue_kv = [&](int t, int s) {
        const unsigned st = sb + 9216 + s * ASTG + kvd;
        const size_t r = kvb + (size_t)t * 64 * QKVS;
        CPA(st,         g_sh + r + DIMX);      CPA(st + 16,        g_sh + r + DIMX + 8);
        CPA(st + 9216,  g_sh + r + 2 * DIMX);  CPA(st + 9216 + 16, g_sh + r + 2 * DIMX + 8);
        CPA_COMMIT();
    };
    issue_kv(0, 0);
    issue_kv(1, 1);
    issue_kv(2, 2);

    // Q tile (64 rows, hi only) via plain LDG/STS (once)
    {
        size_t go = (size_t)(b * NSEQ + q0 + krow) * QKVS + h * 64 + kq;
        *(uint4*)(sm_raw + kvd)      = *(const uint4*)(g_sh + go);
        *(uint4*)(sm_raw + kvd + 16) = *(const uint4*)(g_sh + go + 8);
    }
    cpa_wait<2>();      // stage 0 arrived (this thread); barrier makes all visible
    __syncthreads();

    // persistent Q frags (1-term)
    const unsigned qA = sb + (unsigned)((g * 16 + (lane & 15)) * 144 + (lane >> 4) * 16);
    unsigned qfh[4][4];
#pragma unroll
    for (int s = 0; s < 4; s++) ldsm4(qfh[s], qA + s * 32);

    float o[8][4];
#pragma unroll
    for (int i = 0; i < 8; i++)
#pragma unroll
        for (int q = 0; q < 4; q++) o[i][q] = 0.f;
    float l0 = 0.f, l1 = 0.f;

    const unsigned kOff = (unsigned)((js * 32 + (lane & 7) + ((lane >> 4) << 3)) * 144 +
                                     ((lane >> 3) & 1) * 16);
    const unsigned vOff = 9216 + (unsigned)(((lane & 15)) * 144 + (lane >> 4) * 16);
    const int r0 = g * 16 + (lane >> 2);

    // ---- prologue: S(0) ----
    float sacc[2][4][4];
#pragma unroll
    for (int jt = 0; jt < 4; jt++)
#pragma unroll
        for (int q = 0; q < 4; q++) sacc[0][jt][q] = 0.f;
    {
        const unsigned khA = sb + 9216 + kOff;   // stage 0
#pragma unroll
        for (int s = 0; s < 4; s++) {
            unsigned kh0[4], kh1[4];
            ldsm4(kh0, khA + s * 32);
            ldsm4(kh1, khA + 2304 + s * 32);
            mmah(sacc[0][0], qfh[s], kh0[0], kh0[1]);
            mmah(sacc[0][1], qfh[s], kh0[2], kh0[3]);
            mmah(sacc[0][2], qfh[s], kh1[0], kh1[1]);
            mmah(sacc[0][3], qfh[s], kh1[2], kh1[3]);
        }
    }

// Per-tile body: softmax(CUR) -> aP; wait tile T+1; issue T+3;
// interleaved sweep: S(T+1) into NXT  +  PV(T) into o.
#define ATTN_BODY(CUR, NXT, T)                                                 \
    {                                                                          \
        unsigned aP[2][4];                                                     \
        _Pragma("unroll")                                                      \
        for (int jt = 0; jt < 4; jt++) {                                       \
            float p0 = ex2(CUR[jt][0]), p1 = ex2(CUR[jt][1]);                  \
            float p2 = ex2(CUR[jt][2]), p3 = ex2(CUR[jt][3]);                  \
            l0 += p0 + p1;                                                     \
            l1 += p2 + p3;                                                     \
            aP[jt >> 1][(jt & 1) * 2 + 0] = u32h(__floats2half2_rn(p0, p1));   \
            aP[jt >> 1][(jt & 1) * 2 + 1] = u32h(__floats2half2_rn(p2, p3));   \
        }                                                                      \
        cpa_wait<1>();                                                         \
        __syncthreads();                                                       \
        if ((T) + 3 < 32) issue_kv((T) + 3, ((T) + 3) & 3);                    \
        const unsigned stC = sb + 9216 + ((T) & 3) * ASTG;                     \
        const unsigned stN = sb + 9216 + (((T) + 1) & 3) * ASTG;               \
        const unsigned khA = stN + kOff;                                       \
        const unsigned vhA = stC + vOff;                                       \
        _Pragma("unroll")                                                      \
        for (int jt = 0; jt < 4; jt++) {                                       \
            _Pragma("unroll")                                                  \
            for (int q = 0; q < 4; q++) NXT[jt][q] = 0.f;                      \
        }                                                                      \
        _Pragma("unroll")                                                      \
        for (int i = 0; i < 4; i++) {                                          \
            unsigned kh0[4], kh1[4], va[4], vb[4];                             \
            ldsm4(kh0, khA + i * 32);                                          \
            ldsm4(kh1, khA + 2304 + i * 32);                                   \
            const int sp = i >> 1, db0 = (i & 1) * 2;                          \
            const unsigned vk = vhA + (unsigned)((js * 32 + sp * 16) * 144);   \
            ldsm4t(va, vk + db0 * 32);                                         \
            ldsm4t(vb, vk + db0 * 32 + 32);                                    \
            mmah(NXT[0], qfh[i], kh0[0], kh0[1]);                              \
            mmah(NXT[1], qfh[i], kh0[2], kh0[3]);                              \
            mmah(NXT[2], qfh[i], kh1[0], kh1[1]);                              \
            mmah(NXT[3], qfh[i], kh1[2], kh1[3]);                              \
            mmah(o[2 * db0 + 0], aP[sp], va[0], va[1]);                        \
            mmah(o[2 * db0 + 1], aP[sp], va[2], va[3]);                        \
            mmah(o[2 * db0 + 2], aP[sp], vb[0], vb[1]);                        \
            mmah(o[2 * db0 + 3], aP[sp], vb[2], vb[3]);                        \
        }                                                                      \
    }

#pragma unroll 1
    for (int tt = 0; tt < 16; tt++) {
        const int t0 = 2 * tt, t1 = 2 * tt + 1;
        ATTN_BODY(sacc[0], sacc[1], t0);
        ATTN_BODY(sacc[1], sacc[0], t1);
    }

    // ---- reduce l across quad ----
    l0 += __shfl_xor_sync(0xffffffffu, l0, 1);
    l0 += __shfl_xor_sync(0xffffffffu, l0, 2);
    l1 += __shfl_xor_sync(0xffffffffu, l1, 1);
    l1 += __shfl_xor_sync(0xffffffffu, l1, 2);

    // ---- cross-half (js) reduction via smem float scratch ----
    __syncthreads();
    float* red = (float*)sm_raw;                      // [64][68]
    float* redl = (float*)(sm_raw + 64 * 68 * 4);     // [64]
    if (js == 1) {
#pragma unroll
        for (int dt = 0; dt < 8; dt++) {
            *(float2*)&red[r0 * 68 + dt * 8 + (lane & 3) * 2] = make_float2(o[dt][0], o[dt][1]);
            *(float2*)&red[(r0 + 8) * 68 + dt * 8 + (lane & 3) * 2] = make_float2(o[dt][2], o[dt][3]);
        }
        if ((lane & 3) == 0) { redl[r0] = l0; redl[r0 + 8] = l1; }
    }
    __syncthreads();
    if (js == 0) {
        float inv0 = 1.f / (l0 + redl[r0]);
        float inv1 = 1.f / (l1 + redl[r0 + 8]);
        float* op0 = out + ((size_t)(b * NSEQ + q0 + r0) * HH + h) * DD;
        float* op1 = out + ((size_t)(b * NSEQ + q0 + r0 + 8) * HH + h) * DD;
#pragma unroll
        for (int dt = 0; dt < 8; dt++) {
            float2 e0 = *(const float2*)&red[r0 * 68 + dt * 8 + (lane & 3) * 2];
            float2 e1 = *(const float2*)&red[(r0 + 8) * 68 + dt * 8 + (lane & 3) * 2];
            *(float2*)&op0[dt * 8 + (lane & 3) * 2] =
                make_float2((o[dt][0] + e0.x) * inv0, (o[dt][1] + e0.y) * inv0);
            *(float2*)&op1[dt * 8 + (lane & 3) * 2] =
                make_float2((o[dt][2] + e1.x) * inv1, (o[dt][3] + e1.y) * inv1);
        }
    }
}

// ---------------------------------------------------------------------------
extern "C" void kernel_launch(void* const* d_in, const int* in_sizes, int n_in,
                              void* d_out, int out_size) {
    (void)in_sizes; (void)n_in; (void)out_size;
    const float* x = (const float*)d_in[0];
    const float* w = (const float*)d_in[1];
    float* out = (float*)d_out;

    __half *xh, *xl, *wh;
    cudaGetSymbolAddress((void**)&xh, g_xh);
    cudaGetSymbolAddress((void**)&xl, g_xl);
    cudaGetSymbolAddress((void**)&wh, g_wh);

    const int gemm_smem = 3 * GSTG;                 // 92160
    const int attn_smem = 9216 + 4 * ASTG;          // 82944
    cudaFuncSetAttribute((const void*)qkv_gemm,
                         cudaFuncAttributeMaxDynamicSharedMemorySize, gemm_smem);
    cudaFuncSetAttribute((const void*)attn,
                         cudaFuncAttributeMaxDynamicSharedMemorySize, attn_smem);

    split_hl<<<(GM * GK / 4 + 255) / 256, 256>>>(x, xh, xl, GM * GK / 4);
    split_h<<<(GN * GK / 4 + 255) / 256, 256>>>(w, wh, GN * GK / 4);

    dim3 g1(GN / 128, GM / 128);           // (24, 32)
    qkv_gemm<<<g1, 256, gemm_smem>>>();

    dim3 g2(NSEQ / 64, HH, BB);            // (32, 16, 2)
    attn<<<g2, 256, attn_smem>>>(out);
}

// round 11
// speedup vs baseline: 2.3032x; 1.1239x over previous
#include <cuda_runtime.h>
#include <cuda_fp16.h>

#define BB    2
#define NSEQ  2048
#define DIMX  1024
#define HH    16
#define DD    64
#define QKVS  3072
#define GM    4096
#define GN    3072
#define GK    1024

// fp16 scratch: x hi/lo split, w 1-term, QKV projection output (1-term)
__device__ __half g_xh[(size_t)GM * GK], g_xl[(size_t)GM * GK];
__device__ __half g_wh[(size_t)GN * GK];
__device__ __half g_sh[(size_t)GM * GN];

// ---------------------------------------------------------------------------
// portable PTX helpers (sm_80 feature set only)
// ---------------------------------------------------------------------------
__device__ __forceinline__ unsigned smem_u32(const void* p) {
    unsigned a;
    asm("{ .reg .u64 t; cvta.to.shared.u64 t, %1; cvt.u32.u64 %0, t; }" : "=r"(a) : "l"(p));
    return a;
}
__device__ __forceinline__ void ldsm4(unsigned* r, unsigned a) {
    asm volatile("ldmatrix.sync.aligned.m8n8.x4.shared.b16 {%0,%1,%2,%3}, [%4];"
                 : "=r"(r[0]), "=r"(r[1]), "=r"(r[2]), "=r"(r[3]) : "r"(a));
}
__device__ __forceinline__ void ldsm4t(unsigned* r, unsigned a) {
    asm volatile("ldmatrix.sync.aligned.m8n8.x4.trans.shared.b16 {%0,%1,%2,%3}, [%4];"
                 : "=r"(r[0]), "=r"(r[1]), "=r"(r[2]), "=r"(r[3]) : "r"(a));
}
__device__ __forceinline__ void mmah(float* c, const unsigned* a, unsigned b0, unsigned b1) {
    asm volatile("mma.sync.aligned.m16n8k16.row.col.f32.f16.f16.f32 "
                 "{%0,%1,%2,%3}, {%4,%5,%6,%7}, {%8,%9}, {%0,%1,%2,%3};"
                 : "+f"(c[0]), "+f"(c[1]), "+f"(c[2]), "+f"(c[3])
                 : "r"(a[0]), "r"(a[1]), "r"(a[2]), "r"(a[3]), "r"(b0), "r"(b1));
}
__device__ __forceinline__ void split2h(float a, float b, __half2& h, __half2& l) {
    h = __floats2half2_rn(a, b);
    l = __floats2half2_rn(a - __low2float(h), b - __high2float(h));
}
__device__ __forceinline__ unsigned u32h(__half2 v) { return *(unsigned*)&v; }
__device__ __forceinline__ float ex2(float x) {
    float y;
    asm("ex2.approx.f32 %0, %1;" : "=f"(y) : "f"(x));
    return y;
}
#define CPA(dst, src) \
    asm volatile("cp.async.cg.shared.global [%0], [%1], 16;" :: "r"(dst), "l"(src))
#define CPA_COMMIT() asm volatile("cp.async.commit_group;" ::: "memory")
template <int N>
__device__ __forceinline__ void cpa_wait() {
    asm volatile("cp.async.wait_group %0;" :: "n"(N) : "memory");
}

// ---------------------------------------------------------------------------
// Kernel 0a: fp32 -> fp16 hi/lo split (x)
// ---------------------------------------------------------------------------
__global__ __launch_bounds__(256) void split_hl(const float* __restrict__ src,
                                                __half* __restrict__ hi,
                                                __half* __restrict__ lo, int n4) {
    int i = blockIdx.x * 256 + threadIdx.x;
    if (i >= n4) return;
    float4 v = ((const float4*)src)[i];
    __half2 h0, l0, h1, l1;
    split2h(v.x, v.y, h0, l0);
    split2h(v.z, v.w, h1, l1);
    ((__half2*)hi)[i * 2 + 0] = h0;
    ((__half2*)hi)[i * 2 + 1] = h1;
    ((__half2*)lo)[i * 2 + 0] = l0;
    ((__half2*)lo)[i * 2 + 1] = l1;
}
// Kernel 0b: fp32 -> fp16 (1-term, w)
__global__ __launch_bounds__(256) void split_h(const float* __restrict__ src,
                                               __half* __restrict__ hi, int n4) {
    int i = blockIdx.x * 256 + threadIdx.x;
    if (i >= n4) return;
    float4 v = ((const float4*)src)[i];
    ((__half2*)hi)[i * 2 + 0] = __floats2half2_rn(v.x, v.y);
    ((__half2*)hi)[i * 2 + 1] = __floats2half2_rn(v.z, v.w);
}

// ---------------------------------------------------------------------------
// Kernel 1: QKV GEMM, cp.async 3-stage ring. CTA 128x128, K-chunk 32.
// 8 warps = 4(m) x 2(n), warp tile 32x64. Stage (30720 B): Ah 0, Al 10240,
// Bh 20480; pitch 80 B. 2 CTAs/SM.
// PRECISION SPLIT BY OUTPUT: V columns (bn >= 2048) use 2-term (xh+xl)*wh
// because v-rounding passes through to the output at full weight; Q/K columns
// use 1-term (their errors are random across j and softmax-suppressed ~27x).
// Epilogue: 1-term fp16 store; Q region scaled by 0.125/ln2 (for ex2 softmax).
// ---------------------------------------------------------------------------
#define GSTG 30720
#define QSCALE 0.18033688f   // 0.125 / ln(2)
__global__ __launch_bounds__(256, 2) void qkv_gemm() {
    extern __shared__ __align__(16) unsigned char gs[];
    const unsigned sb = smem_u32(gs);
    const int tid = threadIdx.x, lane = tid & 31, wid = tid >> 5;
    const int wm = wid & 3, wn = wid >> 2;
    const int bm = blockIdx.y * 128, bn = blockIdx.x * 128;
    const bool vblk = (bn >= 2 * DIMX);   // V output block -> needs x-lo term

    float acc[2][8][4];
#pragma unroll
    for (int i = 0; i < 2; i++)
#pragma unroll
        for (int j = 0; j < 8; j++)
#pragma unroll
            for (int q = 0; q < 4; q++) acc[i][j][q] = 0.f;

    const int lrow = tid >> 1, lh = (tid & 1) * 16;
    const __half* xh = g_xh + (size_t)(bm + lrow) * GK + lh;
    const __half* xl = g_xl + (size_t)(bm + lrow) * GK + lh;
    const __half* wh = g_wh + (size_t)(bn + lrow) * GK + lh;
    const unsigned drow = lrow * 80 + lh * 2;

    auto issue = [&](int c, int s) {
        const unsigned st = sb + s * GSTG + drow;
        const int ko = c * 32;
        CPA(st,             xh + ko);  CPA(st + 16,         xh + ko + 8);
        if (vblk) {
            CPA(st + 10240,     xl + ko);  CPA(st + 10240 + 16, xl + ko + 8);
        }
        CPA(st + 20480,     wh + ko);  CPA(st + 20480 + 16, wh + ko + 8);
        CPA_COMMIT();
    };

    const unsigned aOff = (unsigned)((wm * 32 + (lane & 15)) * 80 + (lane >> 4) * 16);
    const unsigned bOff = 20480 + (unsigned)((wn * 64 + (lane & 7) + ((lane >> 4) << 3)) * 80 +
                                             ((lane >> 3) & 1) * 16);

    issue(0, 0);
    issue(1, 1);
    int stg = 0;
    for (int c = 0; c < 32; c++) {
        cpa_wait<1>();
        __syncthreads();
        if (c + 2 < 32) {
            int s2 = stg + 2; if (s2 >= 3) s2 -= 3;
            issue(c + 2, s2);
        }
        const unsigned st = sb + stg * GSTG;
        if (++stg == 3) stg = 0;
        const unsigned aAddr = st + aOff, bAddr = st + bOff;
#pragma unroll
        for (int s = 0; s < 2; s++) {
            unsigned ah[2][4], bh[4][4];
            ldsm4(ah[0], aAddr + s * 32);
            ldsm4(ah[1], aAddr + 1280 + s * 32);
#pragma unroll
            for (int np = 0; np < 4; np++) ldsm4(bh[np], bAddr + np * 1280 + s * 32);
            // hi sweep (always)
#pragma unroll
            for (int np = 0; np < 4; np++)
#pragma unroll
                for (int mt = 0; mt < 2; mt++) {
                    mmah(acc[mt][2 * np + 0], ah[mt], bh[np][0], bh[np][1]);
                    mmah(acc[mt][2 * np + 1], ah[mt], bh[np][2], bh[np][3]);
                }
            // lo sweep (V blocks only)
            if (vblk) {
                unsigned al[2][4];
                ldsm4(al[0], aAddr + 10240 + s * 32);
                ldsm4(al[1], aAddr + 10240 + 1280 + s * 32);
#pragma unroll
                for (int np = 0; np < 4; np++)
#pragma unroll
                    for (int mt = 0; mt < 2; mt++) {
                        mmah(acc[mt][2 * np + 0], al[mt], bh[np][0], bh[np][1]);
                        mmah(acc[mt][2 * np + 1], al[mt], bh[np][2], bh[np][3]);
                    }
            }
        }
    }

#pragma unroll
    for (int mt = 0; mt < 2; mt++) {
        int m = bm + wm * 32 + mt * 16 + (lane >> 2);
#pragma unroll
        for (int nt = 0; nt < 8; nt++) {
            int gc = bn + wn * 64 + nt * 8 + ((lane & 3) << 1);
            float sc = (gc < DIMX) ? QSCALE : 1.0f;
            *(__half2*)(g_sh + (size_t)m * GN + gc) =
                __floats2half2_rn(acc[mt][nt][0] * sc, acc[mt][nt][1] * sc);
            *(__half2*)(g_sh + (size_t)(m + 8) * GN + gc) =
                __floats2half2_rn(acc[mt][nt][2] * sc, acc[mt][nt][3] * sc);
        }
    }
}

// ---------------------------------------------------------------------------
// Kernel 2: attention. CTA = (b, h, 64 Q rows); 8 warps = 4 row-groups(16) x
// 2 j-halves(32). 1-term fp16; software-pipelined S(t+1) || PV(t);
// ex2 softmax; cp.async 4-stage K/V ring; ONE sync/tile; 2 CTAs/SM.
// smem bytes (row pitch 144): Qh 0..9216,
//   stage s at 9216+s*18432: Kh +0, Vh +9216. Total 82944.
// ---------------------------------------------------------------------------
#define ASTG 18432
__global__ __launch_bounds__(256, 2) void attn(float* __restrict__ out) {
    extern __shared__ __align__(16) unsigned char sm_raw[];
    const unsigned sb = smem_u32(sm_raw);
    const int tid = threadIdx.x, lane = tid & 31, wid = tid >> 5;
    const int g = wid & 3, js = wid >> 2;
    const int b = blockIdx.z, h = blockIdx.y, q0 = blockIdx.x * 64;

    const int krow = tid >> 2, kq = (tid & 3) * 16;
    const size_t kvb = (size_t)(b * NSEQ + krow) * QKVS + h * 64 + kq;
    const unsigned kvd = (unsigned)((krow * 72 + kq) * 2);
    auto issue_kv = [&](int t, int s) {
        const unsigned st = sb + 9216 + s * ASTG + kvd;
        const size_t r = kvb + (size_t)t * 64 * QKVS;
        CPA(st,         g_sh + r + DIMX);      CPA(st + 16,        g_sh + r + DIMX + 8);
        CPA(st + 9216,  g_sh + r + 2 * DIMX);  CPA(st + 9216 + 16, g_sh + r + 2 * DIMX + 8);
        CPA_COMMIT();
    };
    issue_kv(0, 0);
    issue_kv(1, 1);
    issue_kv(2, 2);

    // Q tile (64 rows, hi only) via plain LDG/STS (once)
    {
        size_t go = (size_t)(b * NSEQ + q0 + krow) * QKVS + h * 64 + kq;
        *(uint4*)(sm_raw + kvd)      = *(const uint4*)(g_sh + go);
        *(uint4*)(sm_raw + kvd + 16) = *(const uint4*)(g_sh + go + 8);
    }
    cpa_wait<2>();
    __syncthreads();

    const unsigned qA = sb + (unsigned)((g * 16 + (lane & 15)) * 144 + (lane >> 4) * 16);
    unsigned qfh[4][4];
#pragma unroll
    for (int s = 0; s < 4; s++) ldsm4(qfh[s], qA + s * 32);

    float o[8][4];
#pragma unroll
    for (int i = 0; i < 8; i++)
#pragma unroll
        for (int q = 0; q < 4; q++) o[i][q] = 0.f;
    float l0 = 0.f, l1 = 0.f;

    const unsigned kOff = (unsigned)((js * 32 + (lane & 7) + ((lane >> 4) << 3)) * 144 +
                                     ((lane >> 3) & 1) * 16);
    const unsigned vOff = 9216 + (unsigned)(((lane & 15)) * 144 + (lane >> 4) * 16);
    const int r0 = g * 16 + (lane >> 2);

    // ---- prologue: S(0) ----
    float sacc[2][4][4];
#pragma unroll
    for (int jt = 0; jt < 4; jt++)
#pragma unroll
        for (int q = 0; q < 4; q++) sacc[0][jt][q] = 0.f;
    {
        const unsigned khA = sb + 9216 + kOff;
#pragma unroll
        for (int s = 0; s < 4; s++) {
            unsigned kh0[4], kh1[4];
            ldsm4(kh0, khA + s * 32);
            ldsm4(kh1, khA + 2304 + s * 32);
            mmah(sacc[0][0], qfh[s], kh0[0], kh0[1]);
            mmah(sacc[0][1], qfh[s], kh0[2], kh0[3]);
            mmah(sacc[0][2], qfh[s], kh1[0], kh1[1]);
            mmah(sacc[0][3], qfh[s], kh1[2], kh1[3]);
        }
    }

#define ATTN_BODY(CUR, NXT, T)                                                 \
    {                                                                          \
        unsigned aP[2][4];                                                     \
        _Pragma("unroll")                                                      \
        for (int jt = 0; jt < 4; jt++) {                                       \
            float p0 = ex2(CUR[jt][0]), p1 = ex2(CUR[jt][1]);                  \
            float p2 = ex2(CUR[jt][2]), p3 = ex2(CUR[jt][3]);                  \
            l0 += p0 + p1;                                                     \
            l1 += p2 + p3;                                                     \
            aP[jt >> 1][(jt & 1) * 2 + 0] = u32h(__floats2half2_rn(p0, p1));   \
            aP[jt >> 1][(jt & 1) * 2 + 1] = u32h(__floats2half2_rn(p2, p3));   \
        }                                                                      \
        cpa_wait<1>();                                                         \
        __syncthreads();                                                       \
        if ((T) + 3 < 32) issue_kv((T) + 3, ((T) + 3) & 3);                    \
        const unsigned stC = sb + 9216 + ((T) & 3) * ASTG;                     \
        const unsigned stN = sb + 9216 + (((T) + 1) & 3) * ASTG;               \
        const unsigned khA = stN + kOff;                                       \
        const unsigned vhA = stC + vOff;                                       \
        _Pragma("unroll")                                                      \
        for (int jt = 0; jt < 4; jt++) {                                       \
            _Pragma("unroll")                                                  \
            for (int q = 0; q < 4; q++) NXT[jt][q] = 0.f;                      \
        }                                                                      \
        _Pragma("unroll")                                                      \
        for (int i = 0; i < 4; i++) {                                          \
            unsigned kh0[4], kh1[4], va[4], vb[4];                             \
            ldsm4(kh0, khA + i * 32);                                          \
            ldsm4(kh1, khA + 2304 + i * 32);                                   \
            const int sp = i >> 1, db0 = (i & 1) * 2;                          \
            const unsigned vk = vhA + (unsigned)((js * 32 + sp * 16) * 144);   \
            ldsm4t(va, vk + db0 * 32);                                         \
            ldsm4t(vb, vk + db0 * 32 + 32);                                    \
            mmah(NXT[0], qfh[i], kh0[0], kh0[1]);                              \
            mmah(NXT[1], qfh[i], kh0[2], kh0[3]);                              \
            mmah(NXT[2], qfh[i], kh1[0], kh1[1]);                              \
            mmah(NXT[3], qfh[i], kh1[2], kh1[3]);                              \
            mmah(o[2 * db0 + 0], aP[sp], va[0], va[1]);                        \
            mmah(o[2 * db0 + 1], aP[sp], va[2], va[3]);                        \
            mmah(o[2 * db0 + 2], aP[sp], vb[0], vb[1]);                        \
            mmah(o[2 * db0 + 3], aP[sp], vb[2], vb[3]);                        \
        }                                                                      \
    }

#pragma unroll 1
    for (int tt = 0; tt < 16; tt++) {
        const int t0 = 2 * tt, t1 = 2 * tt + 1;
        ATTN_BODY(sacc[0], sacc[1], t0);
        ATTN_BODY(sacc[1], sacc[0], t1);
    }

    // ---- reduce l across quad ----
    l0 += __shfl_xor_sync(0xffffffffu, l0, 1);
    l0 += __shfl_xor_sync(0xffffffffu, l0, 2);
    l1 += __shfl_xor_sync(0xffffffffu, l1, 1);
    l1 += __shfl_xor_sync(0xffffffffu, l1, 2);

    // ---- cross-half (js) reduction via smem float scratch ----
    __syncthreads();
    float* red = (float*)sm_raw;                      // [64][68]
    float* redl = (float*)(sm_raw + 64 * 68 * 4);     // [64]
    if (js == 1) {
#pragma unroll
        for (int dt = 0; dt < 8; dt++) {
            *(float2*)&red[r0 * 68 + dt * 8 + (lane & 3) * 2] = make_float2(o[dt][0], o[dt][1]);
            *(float2*)&red[(r0 + 8) * 68 + dt * 8 + (lane & 3) * 2] = make_float2(o[dt][2], o[dt][3]);
        }
        if ((lane & 3) == 0) { redl[r0] = l0; redl[r0 + 8] = l1; }
    }
    __syncthreads();
    if (js == 0) {
        float inv0 = 1.f / (l0 + redl[r0]);
        float inv1 = 1.f / (l1 + redl[r0 + 8]);
        float* op0 = out + ((size_t)(b * NSEQ + q0 + r0) * HH + h) * DD;
        float* op1 = out + ((size_t)(b * NSEQ + q0 + r0 + 8) * HH + h) * DD;
#pragma unroll
        for (int dt = 0; dt < 8; dt++) {
            float2 e0 = *(const float2*)&red[r0 * 68 + dt * 8 + (lane & 3) * 2];
            float2 e1 = *(const float2*)&red[(r0 + 8) * 68 + dt * 8 + (lane & 3) * 2];
            *(float2*)&op0[dt * 8 + (lane & 3) * 2] =
                make_float2((o[dt][0] + e0.x) * inv0, (o[dt][1] + e0.y) * inv0);
            *(float2*)&op1[dt * 8 + (lane & 3) * 2] =
                make_float2((o[dt][2] + e1.x) * inv1, (o[dt][3] + e1.y) * inv1);
        }
    }
}

// ---------------------------------------------------------------------------
extern "C" void kernel_launch(void* const* d_in, const int* in_sizes, int n_in,
                              void* d_out, int out_size) {
    (void)in_sizes; (void)n_in; (void)out_size;
    const float* x = (const float*)d_in[0];
    const float* w = (const float*)d_in[1];
    float* out = (float*)d_out;

    __half *xh, *xl, *wh;
    cudaGetSymbolAddress((void**)&xh, g_xh);
    cudaGetSymbolAddress((void**)&xl, g_xl);
    cudaGetSymbolAddress((void**)&wh, g_wh);

    const int gemm_smem = 3 * GSTG;                 // 92160
    const int attn_smem = 9216 + 4 * ASTG;          // 82944
    cudaFuncSetAttribute((const void*)qkv_gemm,
                         cudaFuncAttributeMaxDynamicSharedMemorySize, gemm_smem);
    cudaFuncSetAttribute((const void*)attn,
                         cudaFuncAttributeMaxDynamicSharedMemorySize, attn_smem);

    split_hl<<<(GM * GK / 4 + 255) / 256, 256>>>(x, xh, xl, GM * GK / 4);
    split_h<<<(GN * GK / 4 + 255) / 256, 256>>>(w, wh, GN * GK / 4);

    dim3 g1(GN / 128, GM / 128);           // (24, 32)
    qkv_gemm<<<g1, 256, gemm_smem>>>();

    dim3 g2(NSEQ / 64, HH, BB);            // (32, 16, 2)
    attn<<<g2, 256, attn_smem>>>(out);
}